// round 16
// baseline (speedup 1.0000x reference)
#include <cuda_runtime.h>
#include <cuda_fp16.h>
#include <math.h>
#include <stdint.h>

// Problem constants (E74DiagonalCell)
#define T_STEPS 2048
#define B_SZ    16
#define DIM_K   1024
#define N_STATE 1024
#define M_ROWS  (T_STEPS * B_SZ)          // 32768
#define STATE_N (B_SZ * N_STATE)          // 16384
#define STATE_N2 (STATE_N / 2)            // 8192 (pair-indexed)
#define EPSF    1e-6f

// GEMM tiling (best measured config: 64x64 warp tile, BK=32)
#define BM 128
#define BN 256
#define BK 32
#define NKT (DIM_K / BK)                   // 32
#define LDS_B 80
#define A_TILE (BM * LDS_B)                // 10240
#define B_TILE (BN * LDS_B)                // 20480
#define OFF_A 0
#define OFF_B A_TILE
#define STAGE_BYTES (A_TILE + B_TILE)      // 30720
#define N_STAGE 4
#define SMEM_TOTAL (N_STAGE * STAGE_BYTES) // 122880 -> 1 CTA/SM

// ---------------------------------------------------------------------------
// Scratch (allocation banned -> __device__ globals)
// ---------------------------------------------------------------------------
__device__ __align__(16) __half g_kh[(size_t)M_ROWS * N_STATE];   // k fp16
__device__ __align__(16) __half g_vh[(size_t)M_ROWS * N_STATE];   // v fp16
__device__ float g_q[(size_t)M_ROWS * N_STATE];                   // q fp32
__device__ float g_ss[M_ROWS];             // sum of squares of k rows

__device__ __align__(16) __half g_xh[(size_t)M_ROWS * DIM_K];
__device__ __align__(16) __half g_wh[(size_t)3 * N_STATE * DIM_K];

// ---------------------------------------------------------------------------
// PTX helpers (compute_80-level)
// ---------------------------------------------------------------------------
__device__ __forceinline__ uint32_t smem_u32(const void* p) {
    uint32_t a;
    asm("{ .reg .u64 t; cvta.to.shared.u64 t, %1; cvt.u32.u64 %0, t; }"
        : "=r"(a) : "l"(p));
    return a;
}

__device__ __forceinline__ void cp_async16(uint32_t dst, const void* src) {
    asm volatile("cp.async.cg.shared.global [%0], [%1], 16;" :: "r"(dst), "l"(src));
}

__device__ __forceinline__ void ldsm4(uint32_t* r, uint32_t addr) {
    asm volatile("ldmatrix.sync.aligned.m8n8.x4.shared.b16 {%0,%1,%2,%3}, [%4];"
                 : "=r"(r[0]), "=r"(r[1]), "=r"(r[2]), "=r"(r[3]) : "r"(addr));
}

__device__ __forceinline__ void mma_f16(float* c, const uint32_t* a,
                                        uint32_t b0, uint32_t b1) {
    asm volatile(
        "mma.sync.aligned.m16n8k16.row.col.f32.f16.f16.f32 "
        "{%0,%1,%2,%3}, {%4,%5,%6,%7}, {%8,%9}, {%0,%1,%2,%3};"
        : "+f"(c[0]), "+f"(c[1]), "+f"(c[2]), "+f"(c[3])
        : "r"(a[0]), "r"(a[1]), "r"(a[2]), "r"(a[3]), "r"(b0), "r"(b1));
}

// Raw MUFU ops
__device__ __forceinline__ float ex2f(float x) {
    float y; asm("ex2.approx.ftz.f32 %0, %1;" : "=f"(y) : "f"(x)); return y;
}
__device__ __forceinline__ float rcpf(float x) {
    float y; asm("rcp.approx.ftz.f32 %0, %1;" : "=f"(y) : "f"(x)); return y;
}

// Streaming 32-bit load (used for half2)
__device__ __forceinline__ uint32_t ldcs_u32(const void* p) {
    uint32_t u;
    asm volatile("ld.global.cs.b32 %0, [%1];" : "=r"(u) : "l"(p));
    return u;
}

#define LOG2E_F   1.4426950408889634f
#define C2LOG2E_F 2.8853900817779268f     // 2*log2(e)

// ---------------------------------------------------------------------------
// fp32 -> fp16 convert, ALL tensors in one launch. Also zeroes g_ss.
// ---------------------------------------------------------------------------
__global__ __launch_bounds__(256) void convert_kernel(
    const float* __restrict__ x,  const float* __restrict__ Wk,
    const float* __restrict__ Wv, const float* __restrict__ Wq)
{
    const int n4x = (M_ROWS * DIM_K) / 4;
    const int n4w = (N_STATE * DIM_K) / 4;
    const int i = blockIdx.x * 256 + threadIdx.x;

    if (i < M_ROWS / 4)
        ((float4*)g_ss)[i] = make_float4(0.f, 0.f, 0.f, 0.f);

    const float* src;
    __half* h;
    int j;
    if (i < n4x) {
        src = x; h = g_xh; j = i;
    } else {
        const int w = (i - n4x) / n4w;           // 0..2
        j = (i - n4x) - w * n4w;
        src = (w == 0) ? Wk : ((w == 1) ? Wv : Wq);
        h = g_wh + (size_t)w * N_STATE * DIM_K;
    }

    const float4 v = ((const float4*)src)[j];
    __half2* hp = (__half2*)h;
    hp[2 * j]     = __floats2half2_rn(v.x, v.y);
    hp[2 * j + 1] = __floats2half2_rn(v.z, v.w);
}

// ---------------------------------------------------------------------------
// cp.async one BK=32 chunk of A (128 rows) and B (256 rows) into a stage.
// ---------------------------------------------------------------------------
__device__ __forceinline__ void issue_loads(
    uint32_t stage, int kt, int m0, int n0, int tid,
    const __half* __restrict__ wh)
{
    const int kc = kt * BK;
    const int r = tid >> 1;
    const int c = (tid & 1) * 2;
    const size_t ga  = (size_t)(m0 + r)       * DIM_K + kc + c * 8;
    const size_t gb0 = (size_t)(n0 + r)       * DIM_K + kc + c * 8;
    const size_t gb1 = (size_t)(n0 + r + 128) * DIM_K + kc + c * 8;
    const uint32_t so  = (uint32_t)(r * LDS_B + c * 16);
    const uint32_t so1 = so + 128u * LDS_B;

    cp_async16(stage + OFF_A + so,       g_xh + ga);
    cp_async16(stage + OFF_A + so + 16,  g_xh + ga + 8);
    cp_async16(stage + OFF_B + so,       wh + gb0);
    cp_async16(stage + OFF_B + so + 16,  wh + gb0 + 8);
    cp_async16(stage + OFF_B + so1,      wh + gb1);
    cp_async16(stage + OFF_B + so1 + 16, wh + gb1 + 8);
}

// ---------------------------------------------------------------------------
// GEMM: C[m,n] = sum_d x[m,d] * W[n,d], single-pass fp16 via mma.sync.
// grid = (4, 256, 3); 256 threads; warp tile 64x64.
// ---------------------------------------------------------------------------
__global__ __launch_bounds__(256, 1) void gemm_mma_kernel()
{
    extern __shared__ __align__(16) char smem[];
    const int tid  = threadIdx.x;
    const int lane = tid & 31;
    const int wid  = tid >> 5;
    const int n0 = blockIdx.x * BN;
    const int m0 = blockIdx.y * BM;
    const int z  = blockIdx.z;

    const __half* wh = g_wh + (size_t)z * N_STATE * DIM_K;

    const uint32_t sb = smem_u32(smem);

    const int wm = (wid & 1) * 64;
    const int wn = (wid >> 1) * 64;

    const int lrow = (lane & 7) + (((lane >> 3) & 1) << 3);  // 0..15
    const int lkB  = (lane >> 4) * 16;                       // 0 or 16

    const uint32_t aRow[4] = {
        (uint32_t)((wm +  0 + lrow) * LDS_B), (uint32_t)((wm + 16 + lrow) * LDS_B),
        (uint32_t)((wm + 32 + lrow) * LDS_B), (uint32_t)((wm + 48 + lrow) * LDS_B) };
    const uint32_t bRow[4] = {
        (uint32_t)((wn +  0 + lrow) * LDS_B), (uint32_t)((wn + 16 + lrow) * LDS_B),
        (uint32_t)((wn + 32 + lrow) * LDS_B), (uint32_t)((wn + 48 + lrow) * LDS_B) };

    float acc[4][8][4];
    #pragma unroll
    for (int i = 0; i < 4; ++i)
        #pragma unroll
        for (int j = 0; j < 8; ++j)
            #pragma unroll
            for (int e = 0; e < 4; ++e) acc[i][j][e] = 0.0f;

    issue_loads(sb,                   0, m0, n0, tid, wh);
    asm volatile("cp.async.commit_group;" ::: "memory");
    issue_loads(sb + STAGE_BYTES,     1, m0, n0, tid, wh);
    asm volatile("cp.async.commit_group;" ::: "memory");
    issue_loads(sb + 2 * STAGE_BYTES, 2, m0, n0, tid, wh);
    asm volatile("cp.async.commit_group;" ::: "memory");

    for (int kt = 0; kt < NKT; ++kt) {
        if (kt < NKT - 2)      asm volatile("cp.async.wait_group 2;" ::: "memory");
        else if (kt < NKT - 1) asm volatile("cp.async.wait_group 1;" ::: "memory");
        else                   asm volatile("cp.async.wait_group 0;" ::: "memory");
        __syncthreads();

        if (kt + 3 < NKT) {
            const uint32_t st = sb + (uint32_t)((kt + 3) % N_STAGE) * STAGE_BYTES;
            issue_loads(st, kt + 3, m0, n0, tid, wh);
            asm volatile("cp.async.commit_group;" ::: "memory");
        }

        const uint32_t stage = sb + (uint32_t)(kt % N_STAGE) * STAGE_BYTES;
        const uint32_t aBase = stage + OFF_A + (uint32_t)lkB;
        const uint32_t bBase = stage + OFF_B + (uint32_t)lkB;

        #pragma unroll
        for (int kk = 0; kk < 2; ++kk) {
            const uint32_t kb = (uint32_t)(kk * 32);

            uint32_t af[4][4];
            #pragma unroll
            for (int mi = 0; mi < 4; ++mi) ldsm4(af[mi], aBase + kb + aRow[mi]);
            uint32_t bf[4][4];
            #pragma unroll
            for (int nj = 0; nj < 4; ++nj) ldsm4(bf[nj], bBase + kb + bRow[nj]);

            #pragma unroll
            for (int mi = 0; mi < 4; ++mi)
                #pragma unroll
                for (int ni = 0; ni < 8; ++ni) {
                    const int nj = ni >> 1, p = ni & 1;
                    mma_f16(acc[mi][ni], af[mi], bf[nj][p], bf[nj][p + 2]);
                }
        }
    }
    __syncthreads();

    // Epilogue: fragment rows lane/4 and lane/4+8, cols (lane%4)*2
    const int er = lane >> 2;
    const int ec = (lane & 3) * 2;

    if (z == 2) {
        #pragma unroll
        for (int mi = 0; mi < 4; ++mi)
            #pragma unroll
            for (int ni = 0; ni < 8; ++ni) {
                const size_t row = (size_t)(m0 + wm + mi * 16 + er);
                const size_t col = (size_t)(n0 + wn + ni * 8 + ec);
                *(float2*)(g_q + row * N_STATE + col) =
                    make_float2(acc[mi][ni][0], acc[mi][ni][1]);
                *(float2*)(g_q + (row + 8) * N_STATE + col) =
                    make_float2(acc[mi][ni][2], acc[mi][ni][3]);
            }
    } else {
        __half* H = (z == 0) ? g_kh : g_vh;
        #pragma unroll
        for (int mi = 0; mi < 4; ++mi)
            #pragma unroll
            for (int ni = 0; ni < 8; ++ni) {
                const size_t row = (size_t)(m0 + wm + mi * 16 + er);
                const size_t col = (size_t)(n0 + wn + ni * 8 + ec);
                *(__half2*)(H + row * N_STATE + col) =
                    __floats2half2_rn(acc[mi][ni][0], acc[mi][ni][1]);
                *(__half2*)(H + (row + 8) * N_STATE + col) =
                    __floats2half2_rn(acc[mi][ni][2], acc[mi][ni][3]);
            }
        if (z == 0) {
            #pragma unroll
            for (int mi = 0; mi < 4; ++mi) {
                float slo = 0.0f, shi = 0.0f;
                #pragma unroll
                for (int ni = 0; ni < 8; ++ni) {
                    slo = fmaf(acc[mi][ni][0], acc[mi][ni][0], slo);
                    slo = fmaf(acc[mi][ni][1], acc[mi][ni][1], slo);
                    shi = fmaf(acc[mi][ni][2], acc[mi][ni][2], shi);
                    shi = fmaf(acc[mi][ni][3], acc[mi][ni][3], shi);
                }
                slo += __shfl_xor_sync(0xFFFFFFFFu, slo, 1);
                slo += __shfl_xor_sync(0xFFFFFFFFu, slo, 2);
                shi += __shfl_xor_sync(0xFFFFFFFFu, shi, 1);
                shi += __shfl_xor_sync(0xFFFFFFFFu, shi, 2);
                if ((lane & 3) == 0) {
                    const int row = m0 + wm + mi * 16 + er;
                    atomicAdd(&g_ss[row], slo);
                    atomicAdd(&g_ss[row + 8], shi);
                }
            }
        }
    }
}

// ---------------------------------------------------------------------------
// Sequential scan: TWO states per thread (two independent S-chains,
// compiler-interleaved -> in-thread ILP covers the ~44-cyc chain latency).
// 8192 threads = 128 CTAs x 64 thr (128 SMs). k/v loaded as half2 (full
// sectors), q/out as float2. Static two-buffer pipeline, D=16.
// ---------------------------------------------------------------------------
#define SCAN_D 16

#define SCAN_LOAD(KB, VB, QB, T0)                                        \
    _Pragma("unroll")                                                    \
    for (int d = 0; d < SCAN_D; ++d) {                                   \
        const size_t o = (size_t)((T0) + d) * STATE_N2 + sp2;            \
        KB[d] = ldcs_u32(kp + o);                                        \
        VB[d] = ldcs_u32(vp + o);                                        \
        QB[d] = __ldcs(qp + o);                                          \
    }

#define SCAN_COMPUTE(KB, VB, QB, T0)                                     \
    _Pragma("unroll")                                                    \
    for (int d = 0; d < SCAN_D; ++d) {                                   \
        const float rn = srn[(T0) + d];                                  \
        const float2 kf = __half22float2(*(__half2*)&KB[d]);             \
        const float2 vf = __half22float2(*(__half2*)&VB[d]);             \
        const float2 qf = QB[d];                                         \
        const float kn0 = kf.x * rn,  kn1 = kf.y * rn;                   \
        const float c10 = C2LOG2E_F * fmaf(-kn0, kn0, 1.0f);             \
        const float c11 = C2LOG2E_F * fmaf(-kn1, kn1, 1.0f);             \
        const float c20 = C2LOG2E_F * (vf.x * kn0);                      \
        const float c21 = C2LOG2E_F * (vf.y * kn1);                      \
        const float e0 = ex2f(fmaf(S0, c10, c20));                       \
        const float e1 = ex2f(fmaf(S1, c11, c21));                       \
        const float r0 = rcpf(e0 + 1.0f);                                \
        const float r1 = rcpf(e1 + 1.0f);                                \
        S0 = fmaf(-2.0f, r0, 1.0f);                                      \
        S1 = fmaf(-2.0f, r1, 1.0f);                                      \
        const float Sq0 = S0 * qf.x, Sq1 = S1 * qf.y;                    \
        const float sg0 = rcpf(1.0f + ex2f(-LOG2E_F * Sq0));             \
        const float sg1 = rcpf(1.0f + ex2f(-LOG2E_F * Sq1));             \
        __stcs(op + (size_t)((T0) + d) * STATE_N2 + sp2,                 \
               make_float2(Sq0 * Sq0 * sg0, Sq1 * Sq1 * sg1));           \
    }

__global__ __launch_bounds__(64) void scan_kernel(float* __restrict__ out,
                                                  float* __restrict__ s_final)
{
    __shared__ float srn[T_STEPS];
    const int sp2 = blockIdx.x * 64 + threadIdx.x;   // state-pair index
    const int b = (sp2 * 2) >> 10;                   // whole CTA shares one b

    for (int t = threadIdx.x; t < T_STEPS; t += 64)
        srn[t] = 1.0f / (sqrtf(g_ss[t * B_SZ + b]) + EPSF);
    __syncthreads();

    const uint32_t* __restrict__ kp = (const uint32_t*)g_kh;  // half2 view
    const uint32_t* __restrict__ vp = (const uint32_t*)g_vh;
    const float*    __restrict__ qp0 = g_q;                   // float2 view
    const float2*   __restrict__ qp = (const float2*)qp0;
    float2* __restrict__ op = (float2*)out;

    uint32_t ka[SCAN_D], va[SCAN_D];
    uint32_t kb[SCAN_D], vb[SCAN_D];
    float2 qa[SCAN_D], qb[SCAN_D];

    SCAN_LOAD(ka, va, qa, 0)

    float S0 = 0.0f, S1 = 0.0f;

    for (int t0 = 0; t0 < T_STEPS; t0 += 2 * SCAN_D) {
        SCAN_LOAD(kb, vb, qb, t0 + SCAN_D)
        SCAN_COMPUTE(ka, va, qa, t0)
        if (t0 + 2 * SCAN_D < T_STEPS) {
            SCAN_LOAD(ka, va, qa, t0 + 2 * SCAN_D)
        }
        SCAN_COMPUTE(kb, vb, qb, t0 + SCAN_D)
    }

    if (s_final)
        ((float2*)s_final)[sp2] = make_float2(S0, S1);
}

// ---------------------------------------------------------------------------
// Launch. Serial, single stream (graph-capture-safe). No noops.
// ---------------------------------------------------------------------------
extern "C" void kernel_launch(void* const* d_in, const int* in_sizes, int n_in,
                              void* d_out, int out_size)
{
    const float* x  = (const float*)d_in[0];
    const float* Wk = (const float*)d_in[1];
    const float* Wv = (const float*)d_in[2];
    const float* Wq = (const float*)d_in[3];
    float* out = (float*)d_out;

    // fp32 -> fp16 converts + g_ss zeroing (single launch)
    const int n4tot = (M_ROWS * DIM_K) / 4 + 3 * ((N_STATE * DIM_K) / 4);
    convert_kernel<<<(n4tot + 255) / 256, 256>>>(x, Wk, Wv, Wq);

    // Tensor-core GEMM for k, v, q (+ fused k row-norm partials)
    cudaFuncSetAttribute(gemm_mma_kernel,
                         cudaFuncAttributeMaxDynamicSharedMemorySize, SMEM_TOTAL);
    dim3 ggrid(N_STATE / BN, M_ROWS / BM, 3);
    gemm_mma_kernel<<<ggrid, 256, SMEM_TOTAL>>>();

    // Scan over time: 2 states/thread, 128 CTAs x 64 threads
    float* s_final = nullptr;
    if (out_size >= M_ROWS * N_STATE + STATE_N)
        s_final = out + (size_t)M_ROWS * N_STATE;
    scan_kernel<<<STATE_N2 / 64, 64>>>(out, s_final);
}

// round 17
// speedup vs baseline: 1.0907x; 1.0907x over previous
#include <cuda_runtime.h>
#include <cuda_fp16.h>
#include <math.h>
#include <stdint.h>

// Problem constants (E74DiagonalCell)
#define T_STEPS 2048
#define B_SZ    16
#define DIM_K   1024
#define N_STATE 1024
#define M_ROWS  (T_STEPS * B_SZ)          // 32768
#define STATE_N (B_SZ * N_STATE)          // 16384
#define EPSF    1e-6f

// GEMM tiling: R8 champion config — CTA 128x128, 8 warps of 64x32, BK=32,
// 4-stage cp.async pipeline, 2 CTAs/SM.
#define BM 128
#define BN 128
#define BK 32
#define NKT (DIM_K / BK)                   // 32
#define LDS_B 80                           // padded row stride bytes
#define TILE_BYTES (BM * LDS_B)            // 10240
#define OFF_A 0
#define OFF_B TILE_BYTES
#define STAGE_BYTES (2 * TILE_BYTES)       // 20480
#define N_STAGE 4
#define SMEM_TOTAL (N_STAGE * STAGE_BYTES) // 81920 -> 2 CTAs/SM

// ---------------------------------------------------------------------------
// Scratch (allocation banned -> __device__ globals)
// ---------------------------------------------------------------------------
__device__ __align__(16) __half g_kh[(size_t)M_ROWS * N_STATE];   // k fp16
__device__ __align__(16) __half g_vh[(size_t)M_ROWS * N_STATE];   // v fp16
__device__ float g_q[(size_t)M_ROWS * N_STATE];                   // q fp32
__device__ float g_ss[M_ROWS];             // sum of squares of k rows

__device__ __align__(16) __half g_xh[(size_t)M_ROWS * DIM_K];
__device__ __align__(16) __half g_wh[(size_t)3 * N_STATE * DIM_K];

// ---------------------------------------------------------------------------
// PTX helpers (compute_80-level)
// ---------------------------------------------------------------------------
__device__ __forceinline__ uint32_t smem_u32(const void* p) {
    uint32_t a;
    asm("{ .reg .u64 t; cvta.to.shared.u64 t, %1; cvt.u32.u64 %0, t; }"
        : "=r"(a) : "l"(p));
    return a;
}

__device__ __forceinline__ void cp_async16(uint32_t dst, const void* src) {
    asm volatile("cp.async.cg.shared.global [%0], [%1], 16;" :: "r"(dst), "l"(src));
}

__device__ __forceinline__ void ldsm4(uint32_t* r, uint32_t addr) {
    asm volatile("ldmatrix.sync.aligned.m8n8.x4.shared.b16 {%0,%1,%2,%3}, [%4];"
                 : "=r"(r[0]), "=r"(r[1]), "=r"(r[2]), "=r"(r[3]) : "r"(addr));
}

__device__ __forceinline__ void mma_f16(float* c, const uint32_t* a,
                                        uint32_t b0, uint32_t b1) {
    asm volatile(
        "mma.sync.aligned.m16n8k16.row.col.f32.f16.f16.f32 "
        "{%0,%1,%2,%3}, {%4,%5,%6,%7}, {%8,%9}, {%0,%1,%2,%3};"
        : "+f"(c[0]), "+f"(c[1]), "+f"(c[2]), "+f"(c[3])
        : "r"(a[0]), "r"(a[1]), "r"(a[2]), "r"(a[3]), "r"(b0), "r"(b1));
}

// Raw MUFU ops
__device__ __forceinline__ float ex2f(float x) {
    float y; asm("ex2.approx.ftz.f32 %0, %1;" : "=f"(y) : "f"(x)); return y;
}
__device__ __forceinline__ float rcpf(float x) {
    float y; asm("rcp.approx.ftz.f32 %0, %1;" : "=f"(y) : "f"(x)); return y;
}

// Streaming fp16 load -> float
__device__ __forceinline__ float ldcs_h(const __half* p) {
    unsigned short u;
    asm volatile("ld.global.cs.u16 %0, [%1];" : "=h"(u) : "l"(p));
    return __half2float(__ushort_as_half(u));
}

#define LOG2E_F   1.4426950408889634f
#define C2LOG2E_F 2.8853900817779268f     // 2*log2(e)

// ---------------------------------------------------------------------------
// fp32 -> fp16 convert, ALL tensors in one launch. Also zeroes g_ss.
// ---------------------------------------------------------------------------
__global__ __launch_bounds__(256) void convert_kernel(
    const float* __restrict__ x,  const float* __restrict__ Wk,
    const float* __restrict__ Wv, const float* __restrict__ Wq)
{
    const int n4x = (M_ROWS * DIM_K) / 4;
    const int n4w = (N_STATE * DIM_K) / 4;
    const int i = blockIdx.x * 256 + threadIdx.x;

    if (i < M_ROWS / 4)
        ((float4*)g_ss)[i] = make_float4(0.f, 0.f, 0.f, 0.f);

    const float* src;
    __half* h;
    int j;
    if (i < n4x) {
        src = x; h = g_xh; j = i;
    } else {
        const int w = (i - n4x) / n4w;           // 0..2
        j = (i - n4x) - w * n4w;
        src = (w == 0) ? Wk : ((w == 1) ? Wv : Wq);
        h = g_wh + (size_t)w * N_STATE * DIM_K;
    }

    const float4 v = ((const float4*)src)[j];
    __half2* hp = (__half2*)h;
    hp[2 * j]     = __floats2half2_rn(v.x, v.y);
    hp[2 * j + 1] = __floats2half2_rn(v.z, v.w);
}

// ---------------------------------------------------------------------------
// cp.async one BK=32 chunk of A and B tiles (128 rows each) into a stage.
// Each thread: row r = tid/2, 16B chunk c = (tid&1)*2 -> 4 cp.async.
// ---------------------------------------------------------------------------
__device__ __forceinline__ void issue_loads(
    uint32_t stage, int kt, int m0, int n0, int tid,
    const __half* __restrict__ wh)
{
    const int kc = kt * BK;
    const int r = tid >> 1;
    const int c = (tid & 1) * 2;
    const size_t ga = (size_t)(m0 + r) * DIM_K + kc + c * 8;
    const size_t gb = (size_t)(n0 + r) * DIM_K + kc + c * 8;
    const uint32_t so = (uint32_t)(r * LDS_B + c * 16);

    cp_async16(stage + OFF_A + so,      g_xh + ga);
    cp_async16(stage + OFF_A + so + 16, g_xh + ga + 8);
    cp_async16(stage + OFF_B + so,      wh + gb);
    cp_async16(stage + OFF_B + so + 16, wh + gb + 8);
}

// ---------------------------------------------------------------------------
// GEMM: C[m,n] = sum_d x[m,d] * W[n,d], single-pass fp16 via mma.sync.
// grid = (N/BN=8, M/BM=256, 3); 256 threads; warp tile 64x32; 2 CTAs/SM.
// Epilogue: z=0 -> g_kh fp16 + fused row sum-of-squares atomics into g_ss;
//           z=1 -> g_vh fp16; z=2 -> g_q fp32.
// ---------------------------------------------------------------------------
__global__ __launch_bounds__(256, 2) void gemm_mma_kernel()
{
    extern __shared__ __align__(16) char smem[];
    const int tid  = threadIdx.x;
    const int lane = tid & 31;
    const int wid  = tid >> 5;
    const int n0 = blockIdx.x * BN;
    const int m0 = blockIdx.y * BM;
    const int z  = blockIdx.z;

    const __half* wh = g_wh + (size_t)z * N_STATE * DIM_K;

    const uint32_t sb = smem_u32(smem);

    const int wm = (wid & 1) * 64;
    const int wn = (wid >> 1) * 32;

    const int lrow = (lane & 7) + (((lane >> 3) & 1) << 3);  // 0..15
    const int lkB  = (lane >> 4) * 16;                       // 0 or 16

    float acc[4][4][4];
    #pragma unroll
    for (int i = 0; i < 4; ++i)
        #pragma unroll
        for (int j = 0; j < 4; ++j)
            #pragma unroll
            for (int e = 0; e < 4; ++e) acc[i][j][e] = 0.0f;

    // Prologue: fill stages 0..2
    issue_loads(sb,                   0, m0, n0, tid, wh);
    asm volatile("cp.async.commit_group;" ::: "memory");
    issue_loads(sb + STAGE_BYTES,     1, m0, n0, tid, wh);
    asm volatile("cp.async.commit_group;" ::: "memory");
    issue_loads(sb + 2 * STAGE_BYTES, 2, m0, n0, tid, wh);
    asm volatile("cp.async.commit_group;" ::: "memory");

    for (int kt = 0; kt < NKT; ++kt) {
        if (kt < NKT - 2)      asm volatile("cp.async.wait_group 2;" ::: "memory");
        else if (kt < NKT - 1) asm volatile("cp.async.wait_group 1;" ::: "memory");
        else                   asm volatile("cp.async.wait_group 0;" ::: "memory");
        __syncthreads();

        if (kt + 3 < NKT) {
            const uint32_t st = sb + (uint32_t)((kt + 3) % N_STAGE) * STAGE_BYTES;
            issue_loads(st, kt + 3, m0, n0, tid, wh);
            asm volatile("cp.async.commit_group;" ::: "memory");
        }

        const uint32_t stage = sb + (uint32_t)(kt % N_STAGE) * STAGE_BYTES;

        #pragma unroll
        for (int kk = 0; kk < 2; ++kk) {       // two k16 halves of BK=32
            const uint32_t kb = (uint32_t)(kk * 32 + lkB);

            uint32_t af[4][4];
            #pragma unroll
            for (int mi = 0; mi < 4; ++mi) {
                const uint32_t ra = (uint32_t)((wm + mi * 16 + lrow) * LDS_B) + kb;
                ldsm4(af[mi], stage + OFF_A + ra);
            }
            uint32_t bf[2][4];
            #pragma unroll
            for (int nj = 0; nj < 2; ++nj) {
                const uint32_t rb = (uint32_t)((wn + nj * 16 + lrow) * LDS_B) + kb;
                ldsm4(bf[nj], stage + OFF_B + rb);
            }

            #pragma unroll
            for (int mi = 0; mi < 4; ++mi)
                #pragma unroll
                for (int ni = 0; ni < 4; ++ni) {
                    const int nj = ni >> 1, p = ni & 1;
                    mma_f16(acc[mi][ni], af[mi], bf[nj][p], bf[nj][p + 2]);
                }
        }
    }
    __syncthreads();

    // Epilogue: fragment rows lane/4 and lane/4+8, cols (lane%4)*2
    const int er = lane >> 2;
    const int ec = (lane & 3) * 2;

    if (z == 2) {
        #pragma unroll
        for (int mi = 0; mi < 4; ++mi)
            #pragma unroll
            for (int ni = 0; ni < 4; ++ni) {
                const size_t row = (size_t)(m0 + wm + mi * 16 + er);
                const size_t col = (size_t)(n0 + wn + ni * 8 + ec);
                *(float2*)(g_q + row * N_STATE + col) =
                    make_float2(acc[mi][ni][0], acc[mi][ni][1]);
                *(float2*)(g_q + (row + 8) * N_STATE + col) =
                    make_float2(acc[mi][ni][2], acc[mi][ni][3]);
            }
    } else {
        __half* H = (z == 0) ? g_kh : g_vh;
        #pragma unroll
        for (int mi = 0; mi < 4; ++mi)
            #pragma unroll
            for (int ni = 0; ni < 4; ++ni) {
                const size_t row = (size_t)(m0 + wm + mi * 16 + er);
                const size_t col = (size_t)(n0 + wn + ni * 8 + ec);
                *(__half2*)(H + row * N_STATE + col) =
                    __floats2half2_rn(acc[mi][ni][0], acc[mi][ni][1]);
                *(__half2*)(H + (row + 8) * N_STATE + col) =
                    __floats2half2_rn(acc[mi][ni][2], acc[mi][ni][3]);
            }
        if (z == 0) {
            // Fused row sums-of-squares (fp32, pre-rounding): this CTA covers
            // 32 of the 1024 columns of each row -> partial sums via atomics.
            #pragma unroll
            for (int mi = 0; mi < 4; ++mi) {
                float slo = 0.0f, shi = 0.0f;
                #pragma unroll
                for (int ni = 0; ni < 4; ++ni) {
                    slo = fmaf(acc[mi][ni][0], acc[mi][ni][0], slo);
                    slo = fmaf(acc[mi][ni][1], acc[mi][ni][1], slo);
                    shi = fmaf(acc[mi][ni][2], acc[mi][ni][2], shi);
                    shi = fmaf(acc[mi][ni][3], acc[mi][ni][3], shi);
                }
                slo += __shfl_xor_sync(0xFFFFFFFFu, slo, 1);
                slo += __shfl_xor_sync(0xFFFFFFFFu, slo, 2);
                shi += __shfl_xor_sync(0xFFFFFFFFu, shi, 1);
                shi += __shfl_xor_sync(0xFFFFFFFFu, shi, 2);
                if ((lane & 3) == 0) {
                    const int row = m0 + wm + mi * 16 + er;
                    atomicAdd(&g_ss[row], slo);
                    atomicAdd(&g_ss[row + 8], shi);
                }
            }
        }
    }
}

// ---------------------------------------------------------------------------
// Sequential scan: champion config (R12) — 128 CTAs x 128 thr, 1 state per
// thread, static two-buffer pipeline D=16, fp16 k/v, fp32 q.
// ---------------------------------------------------------------------------
#define SCAN_D 16

#define SCAN_LOAD(KB, VB, QB, T0)                                        \
    _Pragma("unroll")                                                    \
    for (int d = 0; d < SCAN_D; ++d) {                                   \
        const size_t o = (size_t)((T0) + d) * STATE_N;                   \
        KB[d] = ldcs_h(kp + o);                                          \
        VB[d] = ldcs_h(vp + o);                                          \
        QB[d] = __ldcs(qp + o);                                          \
    }

#define SCAN_COMPUTE(KB, VB, QB, T0)                                     \
    _Pragma("unroll")                                                    \
    for (int d = 0; d < SCAN_D; ++d) {                                   \
        const float rn = srn[(T0) + d];                                  \
        const float kn = KB[d] * rn;                                     \
        const float c1 = C2LOG2E_F * fmaf(-kn, kn, 1.0f);                \
        const float c2 = C2LOG2E_F * (VB[d] * kn);                       \
        const float e  = ex2f(fmaf(S, c1, c2));                          \
        const float r  = rcpf(e + 1.0f);                                 \
        S = fmaf(-2.0f, r, 1.0f);                                        \
        const float Sq = S * QB[d];                                      \
        const float sg = rcpf(1.0f + ex2f(-LOG2E_F * Sq));               \
        __stcs(op + (size_t)((T0) + d) * STATE_N, Sq * Sq * sg);         \
    }

__global__ __launch_bounds__(128) void scan_kernel(float* __restrict__ out,
                                                   float* __restrict__ s_final)
{
    __shared__ float srn[T_STEPS];
    const int s = blockIdx.x * 128 + threadIdx.x;    // 0..16383
    const int b = s >> 10;                           // whole CTA shares one b

    for (int t = threadIdx.x; t < T_STEPS; t += 128)
        srn[t] = 1.0f / (sqrtf(g_ss[t * B_SZ + b]) + EPSF);
    __syncthreads();

    const __half* __restrict__ kp = g_kh + s;
    const __half* __restrict__ vp = g_vh + s;
    const float*  __restrict__ qp = g_q + s;
    float* __restrict__ op = out + s;

    float ka[SCAN_D], va[SCAN_D], qa[SCAN_D];
    float kb[SCAN_D], vb[SCAN_D], qb[SCAN_D];

    SCAN_LOAD(ka, va, qa, 0)

    float S = 0.0f;

    for (int t0 = 0; t0 < T_STEPS; t0 += 2 * SCAN_D) {
        SCAN_LOAD(kb, vb, qb, t0 + SCAN_D)
        SCAN_COMPUTE(ka, va, qa, t0)
        if (t0 + 2 * SCAN_D < T_STEPS) {
            SCAN_LOAD(ka, va, qa, t0 + 2 * SCAN_D)
        }
        SCAN_COMPUTE(kb, vb, qb, t0 + SCAN_D)
    }

    if (s_final)
        s_final[s] = S;
}

// ---------------------------------------------------------------------------
// Launch. Serial, single stream (graph-capture-safe). No noops.
// ---------------------------------------------------------------------------
extern "C" void kernel_launch(void* const* d_in, const int* in_sizes, int n_in,
                              void* d_out, int out_size)
{
    const float* x  = (const float*)d_in[0];
    const float* Wk = (const float*)d_in[1];
    const float* Wv = (const float*)d_in[2];
    const float* Wq = (const float*)d_in[3];
    float* out = (float*)d_out;

    // fp32 -> fp16 converts + g_ss zeroing (single launch)
    const int n4tot = (M_ROWS * DIM_K) / 4 + 3 * ((N_STATE * DIM_K) / 4);
    convert_kernel<<<(n4tot + 255) / 256, 256>>>(x, Wk, Wv, Wq);

    // Tensor-core GEMM for k, v, q (+ fused k row-norm partials)
    cudaFuncSetAttribute(gemm_mma_kernel,
                         cudaFuncAttributeMaxDynamicSharedMemorySize, SMEM_TOTAL);
    dim3 ggrid(N_STATE / BN, M_ROWS / BM, 3);
    gemm_mma_kernel<<<ggrid, 256, SMEM_TOTAL>>>();

    // Scan over time
    float* s_final = nullptr;
    if (out_size >= M_ROWS * N_STATE + STATE_N)
        s_final = out + (size_t)M_ROWS * N_STATE;
    scan_kernel<<<STATE_N / 128, 128>>>(out, s_final);
}